// round 6
// baseline (speedup 1.0000x reference)
#include <cuda_runtime.h>
#include <cstdint>

// QuantumCircuitSimulator2: 24 qubits, 8 steps of 4-qubit (16x16 complex) gates.
// 3-step fusion in a 4096-amplitude SMEM tile (float2, skew a = s + (s>>4)).
// Gate-table reads via LDS.128 (the round-4 bottleneck), addresses via additive
// skewed K-constants, Karatsuba complex matvec on fma.rn.f32x2.

#define NQ 24
#define NSTATE (1u << NQ)
#define TILE_BITS 12
#define TILE (1u << TILE_BITS)
#define NBLOCKS (1u << (NQ - TILE_BITS))
#define PLANE (TILE + (TILE >> 4))     // 4352 float2

#define SADDR2(s) ((s) + ((s) >> 4))

typedef unsigned long long u64;

__device__ __forceinline__ u64 fma2(u64 a, u64 b, u64 c) {
    u64 d;
    asm("fma.rn.f32x2 %0, %1, %2, %3;" : "=l"(d) : "l"(a), "l"(b), "l"(c));
    return d;
}
__device__ __forceinline__ u64 add2(u64 a, u64 b) {
    u64 d;
    asm("add.rn.f32x2 %0, %1, %2;" : "=l"(d) : "l"(a), "l"(b));
    return d;
}
__device__ __forceinline__ u64 pack2(float lo, float hi) {
    u64 d;
    asm("mov.b64 %0, {%1, %2};" : "=l"(d) : "f"(lo), "f"(hi));
    return d;
}
__device__ __forceinline__ void unpack2(u64 v, float& lo, float& hi) {
    asm("mov.b64 {%0, %1}, %2;" : "=f"(lo), "=f"(hi) : "l"(v));
}

// One 16x16 complex gate on this thread's group.
// sG: Karatsuba tables (A=gr, B=gr+gi, C=gi-gr), 256 floats each.
// Addresses: skewed-additive, addr = aBase + sum of K_t for set gate bits.
__device__ __forceinline__ void apply_gate(float2* __restrict__ S,
                                           const float* __restrict__ sG,
                                           unsigned aBase, unsigned K0,
                                           unsigned K1, unsigned K2,
                                           unsigned K3) {
    u64 sr2[8], si2[8], u2[8];
#pragma unroll
    for (int kk = 0; kk < 8; kk++) {
        unsigned a0 = aBase + ((kk & 1) ? K1 : 0u) + ((kk & 2) ? K2 : 0u) +
                      ((kk & 4) ? K3 : 0u);
        float2 c0 = S[a0];
        float2 c1 = S[a0 + K0];
        sr2[kk] = pack2(c0.x, c1.x);
        si2[kk] = pack2(c0.y, c1.y);
        u2[kk]  = add2(sr2[kk], si2[kk]);
    }
    const u64 NEG1 = pack2(-1.0f, -1.0f);
#pragma unroll
    for (int j = 0; j < 16; j++) {
        const float4* A4 = reinterpret_cast<const float4*>(sG + j * 16);
        const float4* B4 = reinterpret_cast<const float4*>(sG + 256 + j * 16);
        const float4* C4 = reinterpret_cast<const float4*>(sG + 512 + j * 16);
        u64 a1 = 0ull, a2 = 0ull, a3 = 0ull;
#pragma unroll
        for (int q = 0; q < 4; q++) {
            float4 av = A4[q], bv = B4[q], cv = C4[q];
            a1 = fma2(pack2(av.x, av.y), u2[2 * q], a1);
            a2 = fma2(pack2(bv.x, bv.y), si2[2 * q], a2);
            a3 = fma2(pack2(cv.x, cv.y), sr2[2 * q], a3);
            a1 = fma2(pack2(av.z, av.w), u2[2 * q + 1], a1);
            a2 = fma2(pack2(bv.z, bv.w), si2[2 * q + 1], a2);
            a3 = fma2(pack2(cv.z, cv.w), sr2[2 * q + 1], a3);
        }
        u64 dre = fma2(a2, NEG1, a1);  // a1 - a2  -> re halves
        u64 dim = add2(a1, a3);        // a1 + a3  -> im halves
        float rl, rh, il, ih;
        unpack2(dre, rl, rh);
        unpack2(dim, il, ih);
        unsigned aj = aBase + ((j & 1) ? K0 : 0u) + ((j & 2) ? K1 : 0u) +
                      ((j & 4) ? K2 : 0u) + ((j & 8) ? K3 : 0u);
        S[aj] = make_float2(rl + rh, il + ih);
    }
}

__global__ __launch_bounds__(256, 3)
void qstep3_kernel(const float* __restrict__ src,
                   float* __restrict__ dst,
                   const float* __restrict__ gates,
                   const int* __restrict__ targets_raw,
                   int stepA, int stepB, int stepC) {
    __shared__ __align__(16) float2 S[PLANE];
    __shared__ __align__(16) float sG[3][768];
    __shared__ int pArr[12];        // physical bits of V (ascending)
    __shared__ int slotArr[12];     // SMEM slot of bit pArr[j]
    __shared__ int bK[2][4];        // skew-additive K of gate B/C target slots
    __shared__ int nbArr[2][8];     // non-target slots (ascending): B, C
    __shared__ unsigned uVmask;

    const int tid = threadIdx.x;
    const int ngates = (stepC >= 0) ? 3 : 2;

    // ---- Karatsuba gate tables ----
    {
        int steps[3] = {stepA, stepB, stepC};
        for (int g = 0; g < ngates; g++) {
            const float* gp = gates + (size_t)steps[g] * 512;
            for (int i = tid; i < 768; i += 256) {
                int t = i >> 8;
                int idx = i & 255;
                float gr = gp[idx], gi = gp[256 + idx];
                sG[g][i] = (t == 0) ? gr : ((t == 1) ? (gr + gi) : (gi - gr));
            }
        }
    }

    // ---- per-block setup ----
    if (tid == 0) {
        int stride = (targets_raw[1] == 0 && targets_raw[3] == 0) ? 2 : 1;
        int steps[3] = {stepA, stepB, stepC};
        int q[3][4];
        for (int g = 0; g < ngates; g++)
            for (int t = 0; t < 4; t++)
                q[g][t] = targets_raw[(steps[g] * 4 + t) * stride];

        unsigned U = 0;
        for (int g = 0; g < ngates; g++)
            for (int t = 0; t < 4; t++) U |= 1u << q[g][t];
        unsigned V = U;
        int need = TILE_BITS - __popc(U);
        for (int b = 0; need > 0; b++)
            if (!((V >> b) & 1u)) { V |= 1u << b; need--; }
        uVmask = V;

        int slot_of[24];
        for (int b = 0; b < 24; b++) slot_of[b] = -1;
        for (int t = 0; t < 4; t++) slot_of[q[0][t]] = 8 + t;  // A: slots 8..11
        int hi = 7;
        for (int g = 1; g < ngates; g++)
            for (int t = 0; t < 4; t++)
                if (slot_of[q[g][t]] < 0) slot_of[q[g][t]] = hi--;
        int fs = 0;
        for (int b = 0; b < 24; b++)
            if (((V >> b) & 1u) && slot_of[b] < 0) slot_of[b] = fs++;

        int j = 0;
        for (int b = 0; b < 24; b++)
            if ((V >> b) & 1u) { pArr[j] = b; slotArr[j] = slot_of[b]; j++; }

        for (int g = 1; g < ngates; g++) {
            unsigned tm = 0;
            for (int t = 0; t < 4; t++) {
                unsigned m = 1u << slot_of[q[g][t]];
                bK[g - 1][t] = (int)(m + (m >> 4));  // skew-additive K
                tm |= m;
            }
            int jj = 0;
            for (int s3 = 0; s3 < 12; s3++)
                if (!((tm >> s3) & 1u)) nbArr[g - 1][jj++] = s3;
        }
    }
    __syncthreads();

    // ---- per-thread mappings ----
    const unsigned V = uVmask;
    unsigned outer = 0;
    {
        unsigned ob = blockIdx.x;
        for (int b = 0; b < 24; b++)
            if (!((V >> b) & 1u)) { outer |= (ob & 1u) << b; ob >>= 1; }
    }
    unsigned gLo = 0, sLo = 0;
#pragma unroll
    for (int j = 0; j < 8; j++)
        if ((tid >> j) & 1) { gLo |= 1u << pArr[j]; sLo |= 1u << slotArr[j]; }

    const float* __restrict__ srcRe = src;
    const float* __restrict__ srcIm = src + NSTATE;

    // ---- copy-in: coalesced global -> permuted SMEM (float2) ----
#pragma unroll
    for (int cc = 0; cc < 16; cc++) {
        unsigned gHi = 0, sHi = 0;
#pragma unroll
        for (int jj = 0; jj < 4; jj++)
            if ((cc >> jj) & 1) {
                gHi |= 1u << pArr[8 + jj];
                sHi |= 1u << slotArr[8 + jj];
            }
        unsigned g = outer + gHi + gLo;
        S[SADDR2(sHi + sLo)] = make_float2(srcRe[g], srcIm[g]);
    }
    __syncthreads();

    // ---- gate A: targets at slots 8..11 (gate order), base = tid ----
    // K(m) = m + (m>>4): 256->272, 512->544, 1024->1088, 2048->2176
    apply_gate(S, sG[0], SADDR2((unsigned)tid), 272u, 544u, 1088u, 2176u);
    __syncthreads();

    // ---- gate B ----
    {
        unsigned baseB = 0;
#pragma unroll
        for (int j = 0; j < 8; j++)
            if ((tid >> j) & 1) baseB |= 1u << nbArr[0][j];
        apply_gate(S, sG[1], SADDR2(baseB), (unsigned)bK[0][0],
                   (unsigned)bK[0][1], (unsigned)bK[0][2], (unsigned)bK[0][3]);
    }
    __syncthreads();

    // ---- gate C (optional) ----
    if (ngates == 3) {
        unsigned baseC = 0;
#pragma unroll
        for (int j = 0; j < 8; j++)
            if ((tid >> j) & 1) baseC |= 1u << nbArr[1][j];
        apply_gate(S, sG[2], SADDR2(baseC), (unsigned)bK[1][0],
                   (unsigned)bK[1][1], (unsigned)bK[1][2], (unsigned)bK[1][3]);
        __syncthreads();
    }

    // ---- copy-out ----
    float* __restrict__ dstRe = dst;
    float* __restrict__ dstIm = dst + NSTATE;
#pragma unroll
    for (int cc = 0; cc < 16; cc++) {
        unsigned gHi = 0, sHi = 0;
#pragma unroll
        for (int jj = 0; jj < 4; jj++)
            if ((cc >> jj) & 1) {
                gHi |= 1u << pArr[8 + jj];
                sHi |= 1u << slotArr[8 + jj];
            }
        unsigned g = outer + gHi + gLo;
        float2 v = S[SADDR2(sHi + sLo)];
        dstRe[g] = v.x;
        dstIm[g] = v.y;
    }
}

extern "C" void kernel_launch(void* const* d_in, const int* in_sizes, int n_in,
                              void* d_out, int out_size) {
    const float* state   = (const float*)d_in[0];
    const int*   targets = (const int*)d_in[1];
    const float* gates   = (const float*)d_in[2];
    float*       out     = (float*)d_out;

    dim3 block(256);
    dim3 grid(NBLOCKS);

    qstep3_kernel<<<grid, block>>>(state, out, gates, targets, 0, 1, 2);
    qstep3_kernel<<<grid, block>>>(out, out, gates, targets, 3, 4, 5);
    qstep3_kernel<<<grid, block>>>(out, out, gates, targets, 6, 7, -1);
}